// round 9
// baseline (speedup 1.0000x reference)
#include <cuda_runtime.h>
#include <cstdint>

// SNNQNet bit-exact scalar path, round 6: fused row-pair k-loop.
// B=16384, S=256, H=128, A=18, T=8. One block = 32 batch rows, fully fused.
// Per warp: 2 rows (2w, 2w+1) accumulated in the SAME k loop -> weights loaded once.
// Spike bytes stored as u16 row-pairs in [warp][k] layout.
// u[t] = fma2(w_pair, {s,s}, u[t]) with s in {0,1}: bit-identical to round-1/5
// k-ascending conditional fp32 adds (proven rel_err 9.000283e-8).

constexpr int Bn = 16384;
constexpr int Sn = 256;
constexpr int Hn = 128;
constexpr int An = 18;
constexpr int Tn = 8;

constexpr int BLOCK = 512;   // 16 warps
constexpr int RPB   = 32;    // batch rows per block (2 per warp)
constexpr int GRID  = Bn / RPB;

typedef unsigned long long ull;
typedef unsigned short u16;

// ---- shared memory layout (bytes) ----
constexpr int OFF_WBUF = 0;                        // packed weights 256*64 ull = 128KB
constexpr int OFF_SIN  = 131072;                   // input pair bytes [16][256] u16 = 8KB
constexpr int OFF_HA   = OFF_SIN + 16 * Sn * 2;    // hidden pairs A [16][128] u16 = 4KB
constexpr int OFF_HB   = OFF_HA + 16 * Hn * 2;     // hidden pairs B = 4KB
constexpr int OFF_WOUT = OFF_HB + 16 * Hn * 2;     // W_out f32 [128][18]
constexpr int OFF_BOUT = OFF_WOUT + Hn * An * 4;   // b_out (32 floats)
constexpr int OFF_CB   = OFF_BOUT + 32 * 4;        // bias/gamma/beta 3*128
constexpr int OFF_LUT  = OFF_CB + 3 * Hn * 4;      // spike LUT [256][8] ull = 16KB
constexpr int SMEM_BYTES = OFF_LUT + 256 * 8 * 8;  // 174720

__device__ __forceinline__ float f2lo(ull v) { return __uint_as_float((unsigned)v); }
__device__ __forceinline__ float f2hi(ull v) { return __uint_as_float((unsigned)(v >> 32)); }
__device__ __forceinline__ ull pk(float a, float b) {
    return (ull)__float_as_uint(a) | ((ull)__float_as_uint(b) << 32);
}

__device__ __forceinline__ void fmad2(ull& u, ull w, ull s) {
    asm("fma.rn.f32x2 %0, %1, %2, %0;" : "+l"(u) : "l"(w), "l"(s));
}

// 16 fma2: 8 timesteps x 2 h-pairs, one k step, one row.
__device__ __forceinline__ void fma8(ull* u0, ull* u1, ull w0, ull w1,
                                     const ulonglong2* __restrict__ lp) {
    ulonglong2 sA = lp[0], sB = lp[1], sC = lp[2], sD = lp[3];
    fmad2(u0[0], w0, sA.x); fmad2(u1[0], w1, sA.x);
    fmad2(u0[1], w0, sA.y); fmad2(u1[1], w1, sA.y);
    fmad2(u0[2], w0, sB.x); fmad2(u1[2], w1, sB.x);
    fmad2(u0[3], w0, sB.y); fmad2(u1[3], w1, sB.y);
    fmad2(u0[4], w0, sC.x); fmad2(u1[4], w1, sC.x);
    fmad2(u0[5], w0, sC.y); fmad2(u1[5], w1, sC.y);
    fmad2(u0[6], w0, sD.x); fmad2(u1[6], w1, sD.x);
    fmad2(u0[7], w0, sD.y); fmad2(u1[7], w1, sD.y);
}

// Fused 2-row GEMM over K (k ascending; weights loaded once per pair).
template <int K>
__device__ __forceinline__ void gemm2(const ull* __restrict__ wbuf,
                                      const u16* __restrict__ sp,  // [K] pair bytes
                                      const ull* __restrict__ lut, int lane,
                                      ull bi0, ull bi1, ull* A0, ull* A1, ull* B0,
                                      ull* B1) {
#pragma unroll
    for (int t = 0; t < Tn; t++) { A0[t] = bi0; A1[t] = bi1; B0[t] = bi0; B1[t] = bi1; }
    const ull* wk = wbuf + lane;
#pragma unroll 1
    for (int k4 = 0; k4 < K; k4 += 4) {
        ull b4 = *(const ull*)(sp + k4);  // 4 k's of row-pair bytes
#pragma unroll
        for (int j = 0; j < 4; j++) {
            unsigned pr = (unsigned)(b4 >> (16 * j)) & 0xFFFFu;
            ull w0 = wk[(k4 + j) * 64];
            ull w1 = wk[(k4 + j) * 64 + 32];
            fma8(A0, A1, w0, w1, (const ulonglong2*)(lut + (pr & 0xFFu) * 8));
            fma8(B0, B1, w0, w1, (const ulonglong2*)(lut + (pr >> 8) * 8));
        }
    }
}

// Butterfly-reduce 8 floats across the warp.
__device__ __forceinline__ void wred8(float* p) {
#pragma unroll
    for (int off = 16; off > 0; off >>= 1) {
#pragma unroll
        for (int t = 0; t < Tn; t++)
            p[t] += __shfl_xor_sync(0xffffffffu, p[t], off);
    }
}

// LN + residual + LIF for one row given its accumulators; returns 4 spike bytes.
__device__ __forceinline__ void ln_lif_row(ull* u0, ull* u1, const float* cb,
                                           unsigned q0, unsigned q1, unsigned q2,
                                           unsigned q3, int lane, unsigned* nout) {
    float p[Tn];
#pragma unroll
    for (int t = 0; t < Tn; t++)
        p[t] = f2lo(u0[t]) + f2hi(u0[t]) + f2lo(u1[t]) + f2hi(u1[t]);
    wred8(p);
    float mu[Tn];
#pragma unroll
    for (int t = 0; t < Tn; t++) mu[t] = p[t] * (1.0f / 128.0f);
#pragma unroll
    for (int t = 0; t < Tn; t++) {
        float a = f2lo(u0[t]) - mu[t];
        float b = f2hi(u0[t]) - mu[t];
        float c = f2lo(u1[t]) - mu[t];
        float d = f2hi(u1[t]) - mu[t];
        p[t] = a * a + b * b + c * c + d * d;
    }
    wred8(p);
    const float g0 = cb[128 + lane],      g1 = cb[128 + lane + 64];
    const float g2 = cb[128 + lane + 32], g3 = cb[128 + lane + 96];
    const float e0 = cb[256 + lane],      e1 = cb[256 + lane + 64];
    const float e2 = cb[256 + lane + 32], e3 = cb[256 + lane + 96];
    float v0 = 0.f, v1 = 0.f, v2 = 0.f, v3 = 0.f;
    unsigned n0 = 0, n1 = 0, n2 = 0, n3 = 0;
#pragma unroll
    for (int t = 0; t < Tn; t++) {
        float rs = rsqrtf(p[t] * (1.0f / 128.0f) + 1e-5f);
        float y0 = (f2lo(u0[t]) - mu[t]) * rs * g0 + e0 + (float)((q0 >> t) & 1);
        float y1 = (f2hi(u0[t]) - mu[t]) * rs * g1 + e1 + (float)((q1 >> t) & 1);
        float y2 = (f2lo(u1[t]) - mu[t]) * rs * g2 + e2 + (float)((q2 >> t) & 1);
        float y3 = (f2hi(u1[t]) - mu[t]) * rs * g3 + e3 + (float)((q3 >> t) & 1);
        v0 += (y0 - v0) * 0.5f; if (v0 >= 1.f) { n0 |= 1u << t; v0 = 0.f; }
        v1 += (y1 - v1) * 0.5f; if (v1 >= 1.f) { n1 |= 1u << t; v1 = 0.f; }
        v2 += (y2 - v2) * 0.5f; if (v2 >= 1.f) { n2 |= 1u << t; v2 = 0.f; }
        v3 += (y3 - v3) * 0.5f; if (v3 >= 1.f) { n3 |= 1u << t; v3 = 0.f; }
    }
    nout[0] = n0; nout[1] = n1; nout[2] = n2; nout[3] = n3;
}

// Plain LIF (no LN/residual) for phase 1.
__device__ __forceinline__ void lif_row(ull* u0, ull* u1, unsigned* nout) {
    float v0 = 0.f, v1 = 0.f, v2 = 0.f, v3 = 0.f;
    unsigned n0 = 0, n1 = 0, n2 = 0, n3 = 0;
#pragma unroll
    for (int t = 0; t < Tn; t++) {
        float a = f2lo(u0[t]), b = f2hi(u0[t]);
        float c = f2lo(u1[t]), d = f2hi(u1[t]);
        v0 += (a - v0) * 0.5f; if (v0 >= 1.f) { n0 |= 1u << t; v0 = 0.f; }
        v1 += (b - v1) * 0.5f; if (v1 >= 1.f) { n1 |= 1u << t; v1 = 0.f; }
        v2 += (c - v2) * 0.5f; if (v2 >= 1.f) { n2 |= 1u << t; v2 = 0.f; }
        v3 += (d - v3) * 0.5f; if (v3 >= 1.f) { n3 |= 1u << t; v3 = 0.f; }
    }
    nout[0] = n0; nout[1] = n1; nout[2] = n2; nout[3] = n3;
}

// Write both rows' spike bytes as u16 pairs into [warp][128] layout.
__device__ __forceinline__ void store_pair(u16* hout, int warp, int lane,
                                           const unsigned* nA, const unsigned* nB) {
    u16* hp = hout + warp * Hn;
    hp[lane]      = (u16)(nA[0] | (nB[0] << 8));
    hp[lane + 64] = (u16)(nA[1] | (nB[1] << 8));
    hp[lane + 32] = (u16)(nA[2] | (nB[2] << 8));
    hp[lane + 96] = (u16)(nA[3] | (nB[3] << 8));
}

__device__ __forceinline__ void load_w_packed(const float* __restrict__ W, int K,
                                              ull* wbuf) {
    float* wf = (float*)wbuf;
    for (int i = threadIdx.x; i < K * Hn; i += BLOCK) {
        int k = i >> 7;
        int h = i & 127;
        wf[(k * 64 + (h & 63)) * 2 + (h >> 6)] = W[i];
    }
}

__device__ __forceinline__ void load_cb3(const float* __restrict__ b,
                                         const float* __restrict__ g,
                                         const float* __restrict__ be, float* cb) {
    for (int i = threadIdx.x; i < Hn; i += BLOCK) {
        cb[i] = b[i];
        cb[128 + i] = g[i];
        cb[256 + i] = be[i];
    }
}

// One MS_ResBlock for the warp's row pair.
__device__ __forceinline__ void resblock2(const ull* __restrict__ wbuf,
                                          const float* __restrict__ cb,
                                          const ull* __restrict__ lut,
                                          const u16* __restrict__ hin,
                                          u16* __restrict__ hout, int warp, int lane) {
    const ull bi0 = pk(cb[lane], cb[lane + 64]);
    const ull bi1 = pk(cb[lane + 32], cb[lane + 96]);
    ull A0[Tn], A1[Tn], B0[Tn], B1[Tn];
    gemm2<Hn>(wbuf, hin + warp * Hn, lut, lane, bi0, bi1, A0, A1, B0, B1);

    const u16* hp = hin + warp * Hn;
    unsigned p0 = hp[lane], p1 = hp[lane + 64], p2 = hp[lane + 32], p3 = hp[lane + 96];
    unsigned nA[4], nB[4];
    ln_lif_row(A0, A1, cb, p0 & 0xFFu, p1 & 0xFFu, p2 & 0xFFu, p3 & 0xFFu, lane, nA);
    ln_lif_row(B0, B1, cb, p0 >> 8, p1 >> 8, p2 >> 8, p3 >> 8, lane, nB);
    store_pair(hout, warp, lane, nA, nB);
}

__global__ __launch_bounds__(BLOCK, 1) void snn_kernel(
    const float* __restrict__ x, const float* __restrict__ enc,
    const float* __restrict__ W_in, const float* __restrict__ b_in,
    const float* __restrict__ W_r1, const float* __restrict__ b_r1,
    const float* __restrict__ g_r1, const float* __restrict__ be_r1,
    const float* __restrict__ W_r2, const float* __restrict__ b_r2,
    const float* __restrict__ g_r2, const float* __restrict__ be_r2,
    const float* __restrict__ W_out, const float* __restrict__ b_out,
    float* __restrict__ out) {
    extern __shared__ char smem[];
    ull* wbuf = (ull*)(smem + OFF_WBUF);
    u16* sIN = (u16*)(smem + OFF_SIN);
    u16* hA = (u16*)(smem + OFF_HA);
    u16* hB = (u16*)(smem + OFF_HB);
    float* wout = (float*)(smem + OFF_WOUT);
    float* bout = (float*)(smem + OFF_BOUT);
    float* cb = (float*)(smem + OFF_CB);
    ull* lut = (ull*)(smem + OFF_LUT);

    const int b0 = blockIdx.x * RPB;
    const int tid = threadIdx.x;
    const int warp = tid >> 5;
    const int lane = tid & 31;

    // Phase 0: spike LUT, Poisson encode (pair layout), stage weights/constants
    for (int i = tid; i < 256 * 8; i += BLOCK) {
        int byte = i >> 3, t = i & 7;
        unsigned u = ((byte >> t) & 1) ? 0x3F800000u : 0u;
        lut[i] = ((ull)u << 32) | u;
    }
    for (int i = tid; i < 16 * Sn; i += BLOCK) {
        int w = i >> 8;
        int s = i & 255;
        int bA = b0 + 2 * w, bB = bA + 1;
        float xA = x[(size_t)bA * Sn + s];
        float xB = x[(size_t)bB * Sn + s];
        unsigned byA = 0, byB = 0;
#pragma unroll
        for (int t = 0; t < Tn; t++) {
            float eA = enc[((size_t)t * Bn + bA) * Sn + s];
            float eB = enc[((size_t)t * Bn + bB) * Sn + s];
            if (eA <= xA) byA |= 1u << t;
            if (eB <= xB) byB |= 1u << t;
        }
        sIN[i] = (u16)(byA | (byB << 8));
    }
    load_w_packed(W_in, Sn, wbuf);
    for (int i = tid; i < Hn; i += BLOCK) cb[i] = b_in[i];
    for (int i = tid; i < Hn * An; i += BLOCK) wout[i] = W_out[i];
    if (tid < An) bout[tid] = b_out[tid];
    __syncthreads();

    // Phase 1: GEMM1 (S=256 -> H=128) + LIF -> hA
    {
        const ull bi0 = pk(cb[lane], cb[lane + 64]);
        const ull bi1 = pk(cb[lane + 32], cb[lane + 96]);
        ull A0[Tn], A1[Tn], B0[Tn], B1[Tn];
        gemm2<Sn>(wbuf, sIN + warp * Sn, lut, lane, bi0, bi1, A0, A1, B0, B1);
        unsigned nA[4], nB[4];
        lif_row(A0, A1, nA);
        lif_row(B0, B1, nB);
        store_pair(hA, warp, lane, nA, nB);
    }
    __syncthreads();

    // Phase 2: ResBlock 1
    load_w_packed(W_r1, Hn, wbuf);
    load_cb3(b_r1, g_r1, be_r1, cb);
    __syncthreads();
    resblock2(wbuf, cb, lut, hA, hB, warp, lane);
    __syncthreads();

    // Phase 3: ResBlock 2
    load_w_packed(W_r2, Hn, wbuf);
    load_cb3(b_r2, g_r2, be_r2, cb);
    __syncthreads();
    resblock2(wbuf, cb, lut, hB, hA, warp, lane);
    __syncthreads();

    // Phase 4: readout GEMM (H=128 -> A=18) + non-spiking LIF + time mean.
    const float WGT[Tn] = {255.f / 2048.f, 127.f / 1024.f, 63.f / 512.f, 31.f / 256.f,
                           15.f / 128.f,   7.f / 64.f,     3.f / 32.f,   1.f / 16.f};
    const unsigned char* hby = (const unsigned char*)hA;
    for (int task = tid; task < RPB * An; task += BLOCK) {
        int r = task / An;
        int a = task - r * An;
        float acc[Tn] = {0.f, 0.f, 0.f, 0.f, 0.f, 0.f, 0.f, 0.f};
        const unsigned char* hp = hby + (r >> 1) * 256 + (r & 1);
        for (int h = 0; h < Hn; h++) {
            unsigned byte = hp[h * 2];
            float w = wout[h * An + a];
#pragma unroll
            for (int t = 0; t < Tn; t++)
                if (byte & (1u << t)) acc[t] += w;
        }
        float bo = bout[a];
        float o = 0.f;
#pragma unroll
        for (int t = 0; t < Tn; t++) o += WGT[t] * (acc[t] + bo);
        out[(size_t)(b0 + r) * An + a] = o;
    }
}

extern "C" void kernel_launch(void* const* d_in, const int* in_sizes, int n_in,
                              void* d_out, int out_size) {
    const float* x     = (const float*)d_in[0];
    const float* enc   = (const float*)d_in[1];
    const float* W_in  = (const float*)d_in[2];
    const float* b_in  = (const float*)d_in[3];
    const float* W_r1  = (const float*)d_in[4];
    const float* b_r1  = (const float*)d_in[5];
    const float* g_r1  = (const float*)d_in[6];
    const float* be_r1 = (const float*)d_in[7];
    const float* W_r2  = (const float*)d_in[8];
    const float* b_r2  = (const float*)d_in[9];
    const float* g_r2  = (const float*)d_in[10];
    const float* be_r2 = (const float*)d_in[11];
    const float* W_out = (const float*)d_in[12];
    const float* b_out = (const float*)d_in[13];
    float* out = (float*)d_out;

    cudaFuncSetAttribute(snn_kernel, cudaFuncAttributeMaxDynamicSharedMemorySize,
                         SMEM_BYTES);
    snn_kernel<<<GRID, BLOCK, SMEM_BYTES>>>(x, enc, W_in, b_in, W_r1, b_r1, g_r1,
                                            be_r1, W_r2, b_r2, g_r2, be_r2, W_out,
                                            b_out, out);
}

// round 10
// speedup vs baseline: 1.5220x; 1.5220x over previous
#include <cuda_runtime.h>
#include <cstdint>

// SNNQNet bit-exact scalar path, round 7: pair-fused k-loop + selective zero-skip
// + vectorized encode. B=16384, S=256, H=128, A=18, T=8.
// One block = 32 batch rows (2 per warp), fully fused, all membranes bit-identical
// to sequential k-ascending fp32 RN adds (proven rel_err 9.000283e-8).

constexpr int Bn = 16384;
constexpr int Sn = 256;
constexpr int Hn = 128;
constexpr int An = 18;
constexpr int Tn = 8;

constexpr int BLOCK = 512;   // 16 warps
constexpr int RPB   = 32;    // batch rows per block (2 per warp)
constexpr int GRID  = Bn / RPB;

typedef unsigned long long ull;
typedef unsigned short u16;

// ---- shared memory layout (bytes) ----
constexpr int OFF_WBUF = 0;                        // packed weights 256*64 ull = 128KB
constexpr int OFF_SIN  = 131072;                   // input pair bytes [16][256] u16 = 8KB
constexpr int OFF_HA   = OFF_SIN + 16 * Sn * 2;    // hidden pairs A [16][128] u16
constexpr int OFF_HB   = OFF_HA + 16 * Hn * 2;     // hidden pairs B
constexpr int OFF_WOUT = OFF_HB + 16 * Hn * 2;     // W_out f32 [128][18]
constexpr int OFF_BOUT = OFF_WOUT + Hn * An * 4;   // b_out (32 floats)
constexpr int OFF_CB   = OFF_BOUT + 32 * 4;        // bias/gamma/beta 3*128
constexpr int OFF_LUT  = OFF_CB + 3 * Hn * 4;      // spike LUT [256][8] ull = 16KB
constexpr int SMEM_BYTES = OFF_LUT + 256 * 8 * 8;  // 174720

__device__ __forceinline__ float f2lo(ull v) { return __uint_as_float((unsigned)v); }
__device__ __forceinline__ float f2hi(ull v) { return __uint_as_float((unsigned)(v >> 32)); }
__device__ __forceinline__ ull pk(float a, float b) {
    return (ull)__float_as_uint(a) | ((ull)__float_as_uint(b) << 32);
}

__device__ __forceinline__ void fmad2(ull& u, ull w, ull s) {
    asm("fma.rn.f32x2 %0, %1, %2, %0;" : "+l"(u) : "l"(w), "l"(s));
}

// 16 fma2: 8 timesteps x 2 h-pairs, one k step, one row.
__device__ __forceinline__ void fma8(ull* u0, ull* u1, ull w0, ull w1,
                                     const ulonglong2* __restrict__ lp) {
    ulonglong2 sA = lp[0], sB = lp[1], sC = lp[2], sD = lp[3];
    fmad2(u0[0], w0, sA.x); fmad2(u1[0], w1, sA.x);
    fmad2(u0[1], w0, sA.y); fmad2(u1[1], w1, sA.y);
    fmad2(u0[2], w0, sB.x); fmad2(u1[2], w1, sB.x);
    fmad2(u0[3], w0, sB.y); fmad2(u1[3], w1, sB.y);
    fmad2(u0[4], w0, sC.x); fmad2(u1[4], w1, sC.x);
    fmad2(u0[5], w0, sC.y); fmad2(u1[5], w1, sC.y);
    fmad2(u0[6], w0, sD.x); fmad2(u1[6], w1, sD.x);
    fmad2(u0[7], w0, sD.y); fmad2(u1[7], w1, sD.y);
}

// Fused 2-row GEMM over K (k ascending; weights loaded once per pair).
// SKIP: branch on quiet bytes (hidden layers, low spike density).
template <int K, bool SKIP>
__device__ __forceinline__ void gemm2(const ull* __restrict__ wbuf,
                                      const u16* __restrict__ sp,  // [K] pair bytes
                                      const ull* __restrict__ lut, int lane,
                                      ull bi0, ull bi1, ull* A0, ull* A1, ull* B0,
                                      ull* B1) {
#pragma unroll
    for (int t = 0; t < Tn; t++) { A0[t] = bi0; A1[t] = bi1; B0[t] = bi0; B1[t] = bi1; }
    const ull* wk = wbuf + lane;
#pragma unroll 1
    for (int k4 = 0; k4 < K; k4 += 4) {
        ull b4 = *(const ull*)(sp + k4);  // 4 k's of row-pair bytes
        if (SKIP && b4 == 0ull) continue;
#pragma unroll
        for (int j = 0; j < 4; j++) {
            unsigned pr = (unsigned)(b4 >> (16 * j)) & 0xFFFFu;
            if (SKIP && pr == 0u) continue;
            ull w0 = wk[(k4 + j) * 64];
            ull w1 = wk[(k4 + j) * 64 + 32];
            if (!SKIP || (pr & 0xFFu))
                fma8(A0, A1, w0, w1, (const ulonglong2*)(lut + (pr & 0xFFu) * 8));
            if (!SKIP || (pr >> 8))
                fma8(B0, B1, w0, w1, (const ulonglong2*)(lut + (pr >> 8) * 8));
        }
    }
}

// Butterfly-reduce 8 floats across the warp.
__device__ __forceinline__ void wred8(float* p) {
#pragma unroll
    for (int off = 16; off > 0; off >>= 1) {
#pragma unroll
        for (int t = 0; t < Tn; t++)
            p[t] += __shfl_xor_sync(0xffffffffu, p[t], off);
    }
}

// LN + residual + LIF for one row given its accumulators; returns 4 spike bytes.
__device__ __forceinline__ void ln_lif_row(ull* u0, ull* u1, const float* cb,
                                           unsigned q0, unsigned q1, unsigned q2,
                                           unsigned q3, int lane, unsigned* nout) {
    float p[Tn];
#pragma unroll
    for (int t = 0; t < Tn; t++)
        p[t] = f2lo(u0[t]) + f2hi(u0[t]) + f2lo(u1[t]) + f2hi(u1[t]);
    wred8(p);
    float mu[Tn];
#pragma unroll
    for (int t = 0; t < Tn; t++) mu[t] = p[t] * (1.0f / 128.0f);
#pragma unroll
    for (int t = 0; t < Tn; t++) {
        float a = f2lo(u0[t]) - mu[t];
        float b = f2hi(u0[t]) - mu[t];
        float c = f2lo(u1[t]) - mu[t];
        float d = f2hi(u1[t]) - mu[t];
        p[t] = a * a + b * b + c * c + d * d;
    }
    wred8(p);
    const float g0 = cb[128 + lane],      g1 = cb[128 + lane + 64];
    const float g2 = cb[128 + lane + 32], g3 = cb[128 + lane + 96];
    const float e0 = cb[256 + lane],      e1 = cb[256 + lane + 64];
    const float e2 = cb[256 + lane + 32], e3 = cb[256 + lane + 96];
    float v0 = 0.f, v1 = 0.f, v2 = 0.f, v3 = 0.f;
    unsigned n0 = 0, n1 = 0, n2 = 0, n3 = 0;
#pragma unroll
    for (int t = 0; t < Tn; t++) {
        float rs = rsqrtf(p[t] * (1.0f / 128.0f) + 1e-5f);
        float y0 = (f2lo(u0[t]) - mu[t]) * rs * g0 + e0 + (float)((q0 >> t) & 1);
        float y1 = (f2hi(u0[t]) - mu[t]) * rs * g1 + e1 + (float)((q1 >> t) & 1);
        float y2 = (f2lo(u1[t]) - mu[t]) * rs * g2 + e2 + (float)((q2 >> t) & 1);
        float y3 = (f2hi(u1[t]) - mu[t]) * rs * g3 + e3 + (float)((q3 >> t) & 1);
        v0 += (y0 - v0) * 0.5f; if (v0 >= 1.f) { n0 |= 1u << t; v0 = 0.f; }
        v1 += (y1 - v1) * 0.5f; if (v1 >= 1.f) { n1 |= 1u << t; v1 = 0.f; }
        v2 += (y2 - v2) * 0.5f; if (v2 >= 1.f) { n2 |= 1u << t; v2 = 0.f; }
        v3 += (y3 - v3) * 0.5f; if (v3 >= 1.f) { n3 |= 1u << t; v3 = 0.f; }
    }
    nout[0] = n0; nout[1] = n1; nout[2] = n2; nout[3] = n3;
}

// Plain LIF (no LN/residual) for phase 1.
__device__ __forceinline__ void lif_row(ull* u0, ull* u1, unsigned* nout) {
    float v0 = 0.f, v1 = 0.f, v2 = 0.f, v3 = 0.f;
    unsigned n0 = 0, n1 = 0, n2 = 0, n3 = 0;
#pragma unroll
    for (int t = 0; t < Tn; t++) {
        float a = f2lo(u0[t]), b = f2hi(u0[t]);
        float c = f2lo(u1[t]), d = f2hi(u1[t]);
        v0 += (a - v0) * 0.5f; if (v0 >= 1.f) { n0 |= 1u << t; v0 = 0.f; }
        v1 += (b - v1) * 0.5f; if (v1 >= 1.f) { n1 |= 1u << t; v1 = 0.f; }
        v2 += (c - v2) * 0.5f; if (v2 >= 1.f) { n2 |= 1u << t; v2 = 0.f; }
        v3 += (d - v3) * 0.5f; if (v3 >= 1.f) { n3 |= 1u << t; v3 = 0.f; }
    }
    nout[0] = n0; nout[1] = n1; nout[2] = n2; nout[3] = n3;
}

// Write both rows' spike bytes as u16 pairs into [warp][128] layout.
__device__ __forceinline__ void store_pair(u16* hout, int warp, int lane,
                                           const unsigned* nA, const unsigned* nB) {
    u16* hp = hout + warp * Hn;
    hp[lane]      = (u16)(nA[0] | (nB[0] << 8));
    hp[lane + 64] = (u16)(nA[1] | (nB[1] << 8));
    hp[lane + 32] = (u16)(nA[2] | (nB[2] << 8));
    hp[lane + 96] = (u16)(nA[3] | (nB[3] << 8));
}

__device__ __forceinline__ void load_w_packed(const float* __restrict__ W, int K,
                                              ull* wbuf) {
    float* wf = (float*)wbuf;
    for (int i = threadIdx.x; i < K * Hn; i += BLOCK) {
        int k = i >> 7;
        int h = i & 127;
        wf[(k * 64 + (h & 63)) * 2 + (h >> 6)] = W[i];
    }
}

__device__ __forceinline__ void load_cb3(const float* __restrict__ b,
                                         const float* __restrict__ g,
                                         const float* __restrict__ be, float* cb) {
    for (int i = threadIdx.x; i < Hn; i += BLOCK) {
        cb[i] = b[i];
        cb[128 + i] = g[i];
        cb[256 + i] = be[i];
    }
}

// One MS_ResBlock for the warp's row pair (SKIP on: hidden spike density low).
__device__ __forceinline__ void resblock2(const ull* __restrict__ wbuf,
                                          const float* __restrict__ cb,
                                          const ull* __restrict__ lut,
                                          const u16* __restrict__ hin,
                                          u16* __restrict__ hout, int warp, int lane) {
    const ull bi0 = pk(cb[lane], cb[lane + 64]);
    const ull bi1 = pk(cb[lane + 32], cb[lane + 96]);
    ull A0[Tn], A1[Tn], B0[Tn], B1[Tn];
    gemm2<Hn, true>(wbuf, hin + warp * Hn, lut, lane, bi0, bi1, A0, A1, B0, B1);

    const u16* hp = hin + warp * Hn;
    unsigned p0 = hp[lane], p1 = hp[lane + 64], p2 = hp[lane + 32], p3 = hp[lane + 96];
    unsigned nA[4], nB[4];
    ln_lif_row(A0, A1, cb, p0 & 0xFFu, p1 & 0xFFu, p2 & 0xFFu, p3 & 0xFFu, lane, nA);
    ln_lif_row(B0, B1, cb, p0 >> 8, p1 >> 8, p2 >> 8, p3 >> 8, lane, nB);
    store_pair(hout, warp, lane, nA, nB);
}

__global__ __launch_bounds__(BLOCK, 1) void snn_kernel(
    const float* __restrict__ x, const float* __restrict__ enc,
    const float* __restrict__ W_in, const float* __restrict__ b_in,
    const float* __restrict__ W_r1, const float* __restrict__ b_r1,
    const float* __restrict__ g_r1, const float* __restrict__ be_r1,
    const float* __restrict__ W_r2, const float* __restrict__ b_r2,
    const float* __restrict__ g_r2, const float* __restrict__ be_r2,
    const float* __restrict__ W_out, const float* __restrict__ b_out,
    float* __restrict__ out) {
    extern __shared__ char smem[];
    ull* wbuf = (ull*)(smem + OFF_WBUF);
    u16* sIN = (u16*)(smem + OFF_SIN);
    u16* hA = (u16*)(smem + OFF_HA);
    u16* hB = (u16*)(smem + OFF_HB);
    float* wout = (float*)(smem + OFF_WOUT);
    float* bout = (float*)(smem + OFF_BOUT);
    float* cb = (float*)(smem + OFF_CB);
    ull* lut = (ull*)(smem + OFF_LUT);

    const int b0 = blockIdx.x * RPB;
    const int tid = threadIdx.x;
    const int warp = tid >> 5;
    const int lane = tid & 31;

    // Phase 0: spike LUT, vectorized Poisson encode (pair layout), stage weights
    for (int i = tid; i < 256 * 8; i += BLOCK) {
        int byte = i >> 3, t = i & 7;
        unsigned u = ((byte >> t) & 1) ? 0x3F800000u : 0u;
        lut[i] = ((ull)u << 32) | u;
    }
    // encode: each iter covers (warp-pair w, 4 consecutive s)
    for (int i = tid; i < 16 * 64; i += BLOCK) {
        int w = i >> 6;
        int s4 = (i & 63) * 4;
        int bA = b0 + 2 * w, bB = bA + 1;
        float4 xA = *(const float4*)(x + (size_t)bA * Sn + s4);
        float4 xB = *(const float4*)(x + (size_t)bB * Sn + s4);
        unsigned byA0 = 0, byA1 = 0, byA2 = 0, byA3 = 0;
        unsigned byB0 = 0, byB1 = 0, byB2 = 0, byB3 = 0;
#pragma unroll
        for (int t = 0; t < Tn; t++) {
            float4 eA = *(const float4*)(enc + ((size_t)t * Bn + bA) * Sn + s4);
            float4 eB = *(const float4*)(enc + ((size_t)t * Bn + bB) * Sn + s4);
            unsigned bit = 1u << t;
            if (eA.x <= xA.x) byA0 |= bit;
            if (eA.y <= xA.y) byA1 |= bit;
            if (eA.z <= xA.z) byA2 |= bit;
            if (eA.w <= xA.w) byA3 |= bit;
            if (eB.x <= xB.x) byB0 |= bit;
            if (eB.y <= xB.y) byB1 |= bit;
            if (eB.z <= xB.z) byB2 |= bit;
            if (eB.w <= xB.w) byB3 |= bit;
        }
        ull packed = (ull)(byA0 | (byB0 << 8)) | ((ull)(byA1 | (byB1 << 8)) << 16) |
                     ((ull)(byA2 | (byB2 << 8)) << 32) | ((ull)(byA3 | (byB3 << 8)) << 48);
        *(ull*)(sIN + w * Sn + s4) = packed;
    }
    load_w_packed(W_in, Sn, wbuf);
    for (int i = tid; i < Hn; i += BLOCK) cb[i] = b_in[i];
    for (int i = tid; i < Hn * An; i += BLOCK) wout[i] = W_out[i];
    if (tid < An) bout[tid] = b_out[tid];
    __syncthreads();

    // Phase 1: GEMM1 (S=256 -> H=128) + LIF -> hA   (dense: spike density 0.5)
    {
        const ull bi0 = pk(cb[lane], cb[lane + 64]);
        const ull bi1 = pk(cb[lane + 32], cb[lane + 96]);
        ull A0[Tn], A1[Tn], B0[Tn], B1[Tn];
        gemm2<Sn, false>(wbuf, sIN + warp * Sn, lut, lane, bi0, bi1, A0, A1, B0, B1);
        unsigned nA[4], nB[4];
        lif_row(A0, A1, nA);
        lif_row(B0, B1, nB);
        store_pair(hA, warp, lane, nA, nB);
    }
    __syncthreads();

    // Phase 2: ResBlock 1
    load_w_packed(W_r1, Hn, wbuf);
    load_cb3(b_r1, g_r1, be_r1, cb);
    __syncthreads();
    resblock2(wbuf, cb, lut, hA, hB, warp, lane);
    __syncthreads();

    // Phase 3: ResBlock 2
    load_w_packed(W_r2, Hn, wbuf);
    load_cb3(b_r2, g_r2, be_r2, cb);
    __syncthreads();
    resblock2(wbuf, cb, lut, hB, hA, warp, lane);
    __syncthreads();

    // Phase 4: readout GEMM (H=128 -> A=18) + non-spiking LIF + time mean.
    const float WGT[Tn] = {255.f / 2048.f, 127.f / 1024.f, 63.f / 512.f, 31.f / 256.f,
                           15.f / 128.f,   7.f / 64.f,     3.f / 32.f,   1.f / 16.f};
    const unsigned char* hby = (const unsigned char*)hA;
    for (int task = tid; task < RPB * An; task += BLOCK) {
        int r = task / An;
        int a = task - r * An;
        float acc[Tn] = {0.f, 0.f, 0.f, 0.f, 0.f, 0.f, 0.f, 0.f};
        const unsigned char* hp = hby + (r >> 1) * 256 + (r & 1);
        for (int h = 0; h < Hn; h++) {
            unsigned byte = hp[h * 2];
            float w = wout[h * An + a];
#pragma unroll
            for (int t = 0; t < Tn; t++)
                if (byte & (1u << t)) acc[t] += w;
        }
        float bo = bout[a];
        float o = 0.f;
#pragma unroll
        for (int t = 0; t < Tn; t++) o += WGT[t] * (acc[t] + bo);
        out[(size_t)(b0 + r) * An + a] = o;
    }
}

extern "C" void kernel_launch(void* const* d_in, const int* in_sizes, int n_in,
                              void* d_out, int out_size) {
    const float* x     = (const float*)d_in[0];
    const float* enc   = (const float*)d_in[1];
    const float* W_in  = (const float*)d_in[2];
    const float* b_in  = (const float*)d_in[3];
    const float* W_r1  = (const float*)d_in[4];
    const float* b_r1  = (const float*)d_in[5];
    const float* g_r1  = (const float*)d_in[6];
    const float* be_r1 = (const float*)d_in[7];
    const float* W_r2  = (const float*)d_in[8];
    const float* b_r2  = (const float*)d_in[9];
    const float* g_r2  = (const float*)d_in[10];
    const float* be_r2 = (const float*)d_in[11];
    const float* W_out = (const float*)d_in[12];
    const float* b_out = (const float*)d_in[13];
    float* out = (float*)d_out;

    cudaFuncSetAttribute(snn_kernel, cudaFuncAttributeMaxDynamicSharedMemorySize,
                         SMEM_BYTES);
    snn_kernel<<<GRID, BLOCK, SMEM_BYTES>>>(x, enc, W_in, b_in, W_r1, b_r1, g_r1,
                                            be_r1, W_r2, b_r2, g_r2, be_r2, W_out,
                                            b_out, out);
}

// round 13
// speedup vs baseline: 1.6215x; 1.0654x over previous
#include <cuda_runtime.h>
#include <cstdint>

// SNNQNet bit-exact scalar path, round 8: 2 CTA/SM occupancy edition.
// B=16384, S=256, H=128, A=18, T=8. One block = 16 batch rows (2 per warp),
// BLOCK=256, smem ~98.6KB -> 2 CTAs/SM (16 warps/SM). W_in staged in two
// 64KB K-chunks with persistent register accumulators: identical adds in
// identical k-ascending order => membranes bit-identical (rel_err 9.000283e-8).

constexpr int Bn = 16384;
constexpr int Sn = 256;
constexpr int Hn = 128;
constexpr int An = 18;
constexpr int Tn = 8;

constexpr int BLOCK = 256;  // 8 warps
constexpr int RPB   = 16;   // batch rows per block (2 per warp)
constexpr int GRID  = Bn / RPB;  // 1024

typedef unsigned long long ull;
typedef unsigned short u16;

// ---- shared memory layout (bytes) ----
constexpr int OFF_WBUF = 0;                        // weight chunk 128*64 ull = 64KB
constexpr int OFF_SIN  = 65536;                    // input pair bytes [8][256] u16 = 4KB
constexpr int OFF_HA   = OFF_SIN + 8 * Sn * 2;     // hidden pairs A [8][128] u16 = 2KB
constexpr int OFF_HB   = OFF_HA + 8 * Hn * 2;      // hidden pairs B = 2KB
constexpr int OFF_WOUT = OFF_HB + 8 * Hn * 2;      // W_out f32 [128][18] = 9216B
constexpr int OFF_BOUT = OFF_WOUT + Hn * An * 4;   // b_out (32 floats)
constexpr int OFF_CB   = OFF_BOUT + 32 * 4;        // bias/gamma/beta 3*128
constexpr int OFF_LUT  = OFF_CB + 3 * Hn * 4;      // spike LUT [256][8] ull = 16KB
constexpr int SMEM_BYTES = OFF_LUT + 256 * 8 * 8;  // 100992 (~98.6KB)

__device__ __forceinline__ float f2lo(ull v) { return __uint_as_float((unsigned)v); }
__device__ __forceinline__ float f2hi(ull v) { return __uint_as_float((unsigned)(v >> 32)); }
__device__ __forceinline__ ull pk(float a, float b) {
    return (ull)__float_as_uint(a) | ((ull)__float_as_uint(b) << 32);
}

__device__ __forceinline__ void fmad2(ull& u, ull w, ull s) {
    asm("fma.rn.f32x2 %0, %1, %2, %0;" : "+l"(u) : "l"(w), "l"(s));
}

// 16 fma2: 8 timesteps x 2 h-pairs, one k step, one row.
__device__ __forceinline__ void fma8(ull* u0, ull* u1, ull w0, ull w1,
                                     const ulonglong2* __restrict__ lp) {
    ulonglong2 sA = lp[0], sB = lp[1], sC = lp[2], sD = lp[3];
    fmad2(u0[0], w0, sA.x); fmad2(u1[0], w1, sA.x);
    fmad2(u0[1], w0, sA.y); fmad2(u1[1], w1, sA.y);
    fmad2(u0[2], w0, sB.x); fmad2(u1[2], w1, sB.x);
    fmad2(u0[3], w0, sB.y); fmad2(u1[3], w1, sB.y);
    fmad2(u0[4], w0, sC.x); fmad2(u1[4], w1, sC.x);
    fmad2(u0[5], w0, sC.y); fmad2(u1[5], w1, sC.y);
    fmad2(u0[6], w0, sD.x); fmad2(u1[6], w1, sD.x);
    fmad2(u0[7], w0, sD.y); fmad2(u1[7], w1, sD.y);
}

// Fused 2-row GEMM over one K-chunk. Accumulators passed in (persist across chunks).
// SKIP: branch on quiet bytes (hidden layers, low spike density).
template <int K, bool SKIP>
__device__ __forceinline__ void gemm2(const ull* __restrict__ wbuf,
                                      const u16* __restrict__ sp,  // [K] pair bytes
                                      const ull* __restrict__ lut, int lane, ull* A0,
                                      ull* A1, ull* B0, ull* B1) {
    const ull* wk = wbuf + lane;
#pragma unroll 1
    for (int k4 = 0; k4 < K; k4 += 4) {
        ull b4 = *(const ull*)(sp + k4);  // 4 k's of row-pair bytes
        if (SKIP && b4 == 0ull) continue;
#pragma unroll
        for (int j = 0; j < 4; j++) {
            unsigned pr = (unsigned)(b4 >> (16 * j)) & 0xFFFFu;
            if (SKIP && pr == 0u) continue;
            ull w0 = wk[(k4 + j) * 64];
            ull w1 = wk[(k4 + j) * 64 + 32];
            if (!SKIP || (pr & 0xFFu))
                fma8(A0, A1, w0, w1, (const ulonglong2*)(lut + (pr & 0xFFu) * 8));
            if (!SKIP || (pr >> 8))
                fma8(B0, B1, w0, w1, (const ulonglong2*)(lut + (pr >> 8) * 8));
        }
    }
}

// Butterfly-reduce 8 floats across the warp.
__device__ __forceinline__ void wred8(float* p) {
#pragma unroll
    for (int off = 16; off > 0; off >>= 1) {
#pragma unroll
        for (int t = 0; t < Tn; t++)
            p[t] += __shfl_xor_sync(0xffffffffu, p[t], off);
    }
}

// LN + residual + LIF for one row given its accumulators; returns 4 spike bytes.
__device__ __forceinline__ void ln_lif_row(ull* u0, ull* u1, const float* cb,
                                           unsigned q0, unsigned q1, unsigned q2,
                                           unsigned q3, int lane, unsigned* nout) {
    float p[Tn];
#pragma unroll
    for (int t = 0; t < Tn; t++)
        p[t] = f2lo(u0[t]) + f2hi(u0[t]) + f2lo(u1[t]) + f2hi(u1[t]);
    wred8(p);
    float mu[Tn];
#pragma unroll
    for (int t = 0; t < Tn; t++) mu[t] = p[t] * (1.0f / 128.0f);
#pragma unroll
    for (int t = 0; t < Tn; t++) {
        float a = f2lo(u0[t]) - mu[t];
        float b = f2hi(u0[t]) - mu[t];
        float c = f2lo(u1[t]) - mu[t];
        float d = f2hi(u1[t]) - mu[t];
        p[t] = a * a + b * b + c * c + d * d;
    }
    wred8(p);
    const float g0 = cb[128 + lane],      g1 = cb[128 + lane + 64];
    const float g2 = cb[128 + lane + 32], g3 = cb[128 + lane + 96];
    const float e0 = cb[256 + lane],      e1 = cb[256 + lane + 64];
    const float e2 = cb[256 + lane + 32], e3 = cb[256 + lane + 96];
    float v0 = 0.f, v1 = 0.f, v2 = 0.f, v3 = 0.f;
    unsigned n0 = 0, n1 = 0, n2 = 0, n3 = 0;
#pragma unroll
    for (int t = 0; t < Tn; t++) {
        float rs = rsqrtf(p[t] * (1.0f / 128.0f) + 1e-5f);
        float y0 = (f2lo(u0[t]) - mu[t]) * rs * g0 + e0 + (float)((q0 >> t) & 1);
        float y1 = (f2hi(u0[t]) - mu[t]) * rs * g1 + e1 + (float)((q1 >> t) & 1);
        float y2 = (f2lo(u1[t]) - mu[t]) * rs * g2 + e2 + (float)((q2 >> t) & 1);
        float y3 = (f2hi(u1[t]) - mu[t]) * rs * g3 + e3 + (float)((q3 >> t) & 1);
        v0 += (y0 - v0) * 0.5f; if (v0 >= 1.f) { n0 |= 1u << t; v0 = 0.f; }
        v1 += (y1 - v1) * 0.5f; if (v1 >= 1.f) { n1 |= 1u << t; v1 = 0.f; }
        v2 += (y2 - v2) * 0.5f; if (v2 >= 1.f) { n2 |= 1u << t; v2 = 0.f; }
        v3 += (y3 - v3) * 0.5f; if (v3 >= 1.f) { n3 |= 1u << t; v3 = 0.f; }
    }
    nout[0] = n0; nout[1] = n1; nout[2] = n2; nout[3] = n3;
}

// Plain LIF (no LN/residual) for phase 1.
__device__ __forceinline__ void lif_row(ull* u0, ull* u1, unsigned* nout) {
    float v0 = 0.f, v1 = 0.f, v2 = 0.f, v3 = 0.f;
    unsigned n0 = 0, n1 = 0, n2 = 0, n3 = 0;
#pragma unroll
    for (int t = 0; t < Tn; t++) {
        float a = f2lo(u0[t]), b = f2hi(u0[t]);
        float c = f2lo(u1[t]), d = f2hi(u1[t]);
        v0 += (a - v0) * 0.5f; if (v0 >= 1.f) { n0 |= 1u << t; v0 = 0.f; }
        v1 += (b - v1) * 0.5f; if (v1 >= 1.f) { n1 |= 1u << t; v1 = 0.f; }
        v2 += (c - v2) * 0.5f; if (v2 >= 1.f) { n2 |= 1u << t; v2 = 0.f; }
        v3 += (d - v3) * 0.5f; if (v3 >= 1.f) { n3 |= 1u << t; v3 = 0.f; }
    }
    nout[0] = n0; nout[1] = n1; nout[2] = n2; nout[3] = n3;
}

// Write both rows' spike bytes as u16 pairs into [warp][128] layout.
__device__ __forceinline__ void store_pair(u16* hout, int warp, int lane,
                                           const unsigned* nA, const unsigned* nB) {
    u16* hp = hout + warp * Hn;
    hp[lane]      = (u16)(nA[0] | (nB[0] << 8));
    hp[lane + 64] = (u16)(nA[1] | (nB[1] << 8));
    hp[lane + 32] = (u16)(nA[2] | (nB[2] << 8));
    hp[lane + 96] = (u16)(nA[3] | (nB[3] << 8));
}

// Stage Kc rows of W (starting at global row k0) into the 64KB chunk buffer.
__device__ __forceinline__ void load_w_chunk(const float* __restrict__ W, int k0,
                                             int Kc, ull* wbuf) {
    float* wf = (float*)wbuf;
    for (int i = threadIdx.x; i < Kc * Hn; i += BLOCK) {
        int k = i >> 7;
        int h = i & 127;
        wf[(k * 64 + (h & 63)) * 2 + (h >> 6)] = W[(k0 + k) * Hn + h];
    }
}

__device__ __forceinline__ void load_cb3(const float* __restrict__ b,
                                         const float* __restrict__ g,
                                         const float* __restrict__ be, float* cb) {
    for (int i = threadIdx.x; i < Hn; i += BLOCK) {
        cb[i] = b[i];
        cb[128 + i] = g[i];
        cb[256 + i] = be[i];
    }
}

// One MS_ResBlock for the warp's row pair (SKIP on).
__device__ __forceinline__ void resblock2(const ull* __restrict__ wbuf,
                                          const float* __restrict__ cb,
                                          const ull* __restrict__ lut,
                                          const u16* __restrict__ hin,
                                          u16* __restrict__ hout, int warp, int lane) {
    const ull bi0 = pk(cb[lane], cb[lane + 64]);
    const ull bi1 = pk(cb[lane + 32], cb[lane + 96]);
    ull A0[Tn], A1[Tn], B0[Tn], B1[Tn];
#pragma unroll
    for (int t = 0; t < Tn; t++) { A0[t] = bi0; A1[t] = bi1; B0[t] = bi0; B1[t] = bi1; }
    gemm2<Hn, true>(wbuf, hin + warp * Hn, lut, lane, A0, A1, B0, B1);

    const u16* hp = hin + warp * Hn;
    unsigned p0 = hp[lane], p1 = hp[lane + 64], p2 = hp[lane + 32], p3 = hp[lane + 96];
    unsigned nA[4], nB[4];
    ln_lif_row(A0, A1, cb, p0 & 0xFFu, p1 & 0xFFu, p2 & 0xFFu, p3 & 0xFFu, lane, nA);
    ln_lif_row(B0, B1, cb, p0 >> 8, p1 >> 8, p2 >> 8, p3 >> 8, lane, nB);
    store_pair(hout, warp, lane, nA, nB);
}

__global__ __launch_bounds__(BLOCK, 2) void snn_kernel(
    const float* __restrict__ x, const float* __restrict__ enc,
    const float* __restrict__ W_in, const float* __restrict__ b_in,
    const float* __restrict__ W_r1, const float* __restrict__ b_r1,
    const float* __restrict__ g_r1, const float* __restrict__ be_r1,
    const float* __restrict__ W_r2, const float* __restrict__ b_r2,
    const float* __restrict__ g_r2, const float* __restrict__ be_r2,
    const float* __restrict__ W_out, const float* __restrict__ b_out,
    float* __restrict__ out) {
    extern __shared__ char smem[];
    ull* wbuf = (ull*)(smem + OFF_WBUF);
    u16* sIN = (u16*)(smem + OFF_SIN);
    u16* hA = (u16*)(smem + OFF_HA);
    u16* hB = (u16*)(smem + OFF_HB);
    float* wout = (float*)(smem + OFF_WOUT);
    float* bout = (float*)(smem + OFF_BOUT);
    float* cb = (float*)(smem + OFF_CB);
    ull* lut = (ull*)(smem + OFF_LUT);

    const int b0 = blockIdx.x * RPB;
    const int tid = threadIdx.x;
    const int warp = tid >> 5;
    const int lane = tid & 31;

    // Phase 0: spike LUT, vectorized Poisson encode (pair layout), stage constants
    for (int i = tid; i < 256 * 8; i += BLOCK) {
        int byte = i >> 3, t = i & 7;
        unsigned u = ((byte >> t) & 1) ? 0x3F800000u : 0u;
        lut[i] = ((ull)u << 32) | u;
    }
    for (int i = tid; i < 8 * 64; i += BLOCK) {
        int w = i >> 6;
        int s4 = (i & 63) * 4;
        int bA = b0 + 2 * w, bB = bA + 1;
        float4 xA = *(const float4*)(x + (size_t)bA * Sn + s4);
        float4 xB = *(const float4*)(x + (size_t)bB * Sn + s4);
        unsigned byA0 = 0, byA1 = 0, byA2 = 0, byA3 = 0;
        unsigned byB0 = 0, byB1 = 0, byB2 = 0, byB3 = 0;
#pragma unroll
        for (int t = 0; t < Tn; t++) {
            float4 eA = *(const float4*)(enc + ((size_t)t * Bn + bA) * Sn + s4);
            float4 eB = *(const float4*)(enc + ((size_t)t * Bn + bB) * Sn + s4);
            unsigned bit = 1u << t;
            if (eA.x <= xA.x) byA0 |= bit;
            if (eA.y <= xA.y) byA1 |= bit;
            if (eA.z <= xA.z) byA2 |= bit;
            if (eA.w <= xA.w) byA3 |= bit;
            if (eB.x <= xB.x) byB0 |= bit;
            if (eB.y <= xB.y) byB1 |= bit;
            if (eB.z <= xB.z) byB2 |= bit;
            if (eB.w <= xB.w) byB3 |= bit;
        }
        ull packed = (ull)(byA0 | (byB0 << 8)) | ((ull)(byA1 | (byB1 << 8)) << 16) |
                     ((ull)(byA2 | (byB2 << 8)) << 32) | ((ull)(byA3 | (byB3 << 8)) << 48);
        *(ull*)(sIN + w * Sn + s4) = packed;
    }
    for (int i = tid; i < Hn; i += BLOCK) cb[i] = b_in[i];
    for (int i = tid; i < Hn * An; i += BLOCK) wout[i] = W_out[i];
    if (tid < An) bout[tid] = b_out[tid];
    __syncthreads();

    // Phase 1: GEMM1 (S=256 -> H=128, two 128-k chunks) + LIF -> hA
    {
        const ull bi0 = pk(cb[lane], cb[lane + 64]);
        const ull bi1 = pk(cb[lane + 32], cb[lane + 96]);
        ull A0[Tn], A1[Tn], B0[Tn], B1[Tn];
#pragma unroll
        for (int t = 0; t < Tn; t++) { A0[t] = bi0; A1[t] = bi1; B0[t] = bi0; B1[t] = bi1; }
#pragma unroll 1
        for (int c = 0; c < 2; c++) {
            load_w_chunk(W_in, c * 128, 128, wbuf);
            __syncthreads();
            gemm2<128, false>(wbuf, sIN + warp * Sn + c * 128, lut, lane, A0, A1, B0, B1);
            __syncthreads();
        }
        unsigned nA[4], nB[4];
        lif_row(A0, A1, nA);
        lif_row(B0, B1, nB);
        store_pair(hA, warp, lane, nA, nB);
    }
    __syncthreads();

    // Phase 2: ResBlock 1
    load_w_chunk(W_r1, 0, Hn, wbuf);
    load_cb3(b_r1, g_r1, be_r1, cb);
    __syncthreads();
    resblock2(wbuf, cb, lut, hA, hB, warp, lane);
    __syncthreads();

    // Phase 3: ResBlock 2
    load_w_chunk(W_r2, 0, Hn, wbuf);
    load_cb3(b_r2, g_r2, be_r2, cb);
    __syncthreads();
    resblock2(wbuf, cb, lut, hB, hA, warp, lane);
    __syncthreads();

    // Phase 4: readout GEMM (H=128 -> A=18) + non-spiking LIF + time mean.
    const float WGT[Tn] = {255.f / 2048.f, 127.f / 1024.f, 63.f / 512.f, 31.f / 256.f,
                           15.f / 128.f,   7.f / 64.f,     3.f / 32.f,   1.f / 16.f};
    const unsigned char* hby = (const unsigned char*)hA;
    for (int task = tid; task < RPB * An; task += BLOCK) {
        int r = task / An;
        int a = task - r * An;
        float acc[Tn] = {0.f, 0.f, 0.f, 0.f, 0.f, 0.f, 0.f, 0.f};
        const unsigned char* hp = hby + (r >> 1) * 256 + (r & 1);
        for (int h = 0; h < Hn; h++) {
            unsigned byte = hp[h * 2];
            float w = wout[h * An + a];
#pragma unroll
            for (int t = 0; t < Tn; t++)
                if (byte & (1u << t)) acc[t] += w;
        }
        float bo = bout[a];
        float o = 0.f;
#pragma unroll
        for (int t = 0; t < Tn; t++) o += WGT[t] * (acc[t] + bo);
        out[(size_t)(b0 + r) * An + a] = o;
    }
}

extern "C" void kernel_launch(void* const* d_in, const int* in_sizes, int n_in,
                              void* d_out, int out_size) {
    const float* x     = (const float*)d_in[0];
    const float* enc   = (const float*)d_in[1];
    const float* W_in  = (const float*)d_in[2];
    const float* b_in  = (const float*)d_in[3];
    const float* W_r1  = (const float*)d_in[4];
    const float* b_r1  = (const float*)d_in[5];
    const float* g_r1  = (const float*)d_in[6];
    const float* be_r1 = (const float*)d_in[7];
    const float* W_r2  = (const float*)d_in[8];
    const float* b_r2  = (const float*)d_in[9];
    const float* g_r2  = (const float*)d_in[10];
    const float* be_r2 = (const float*)d_in[11];
    const float* W_out = (const float*)d_in[12];
    const float* b_out = (const float*)d_in[13];
    float* out = (float*)d_out;

    cudaFuncSetAttribute(snn_kernel, cudaFuncAttributeMaxDynamicSharedMemorySize,
                         SMEM_BYTES);
    snn_kernel<<<GRID, BLOCK, SMEM_BYTES>>>(x, enc, W_in, b_in, W_r1, b_r1, g_r1,
                                            be_r1, W_r2, b_r2, g_r2, be_r2, W_out,
                                            b_out, out);
}

// round 14
// speedup vs baseline: 1.6223x; 1.0005x over previous
#include <cuda_runtime.h>
#include <cstdint>

// SNNQNet bit-exact scalar path, round 9: round-8 kernel + smem carveout fix
// so 2 CTAs/SM actually co-reside (PreferredSharedMemoryCarveout=100).
// B=16384, S=256, H=128, A=18, T=8. One block = 16 batch rows (2 per warp),
// BLOCK=256, smem ~98.6KB. Membranes bit-identical to k-ascending fp32 RN adds
// (proven rel_err 9.000283e-8).

constexpr int Bn = 16384;
constexpr int Sn = 256;
constexpr int Hn = 128;
constexpr int An = 18;
constexpr int Tn = 8;

constexpr int BLOCK = 256;  // 8 warps
constexpr int RPB   = 16;   // batch rows per block (2 per warp)
constexpr int GRID  = Bn / RPB;  // 1024

typedef unsigned long long ull;
typedef unsigned short u16;

// ---- shared memory layout (bytes) ----
constexpr int OFF_WBUF = 0;                        // weight chunk 128*64 ull = 64KB
constexpr int OFF_SIN  = 65536;                    // input pair bytes [8][256] u16 = 4KB
constexpr int OFF_HA   = OFF_SIN + 8 * Sn * 2;     // hidden pairs A [8][128] u16 = 2KB
constexpr int OFF_HB   = OFF_HA + 8 * Hn * 2;      // hidden pairs B = 2KB
constexpr int OFF_WOUT = OFF_HB + 8 * Hn * 2;      // W_out f32 [128][18] = 9216B
constexpr int OFF_BOUT = OFF_WOUT + Hn * An * 4;   // b_out (32 floats)
constexpr int OFF_CB   = OFF_BOUT + 32 * 4;        // bias/gamma/beta 3*128
constexpr int OFF_LUT  = OFF_CB + 3 * Hn * 4;      // spike LUT [256][8] ull = 16KB
constexpr int SMEM_BYTES = OFF_LUT + 256 * 8 * 8;  // 100992 (~98.6KB)

__device__ __forceinline__ float f2lo(ull v) { return __uint_as_float((unsigned)v); }
__device__ __forceinline__ float f2hi(ull v) { return __uint_as_float((unsigned)(v >> 32)); }
__device__ __forceinline__ ull pk(float a, float b) {
    return (ull)__float_as_uint(a) | ((ull)__float_as_uint(b) << 32);
}

__device__ __forceinline__ void fmad2(ull& u, ull w, ull s) {
    asm("fma.rn.f32x2 %0, %1, %2, %0;" : "+l"(u) : "l"(w), "l"(s));
}

// 16 fma2: 8 timesteps x 2 h-pairs, one k step, one row.
__device__ __forceinline__ void fma8(ull* u0, ull* u1, ull w0, ull w1,
                                     const ulonglong2* __restrict__ lp) {
    ulonglong2 sA = lp[0], sB = lp[1], sC = lp[2], sD = lp[3];
    fmad2(u0[0], w0, sA.x); fmad2(u1[0], w1, sA.x);
    fmad2(u0[1], w0, sA.y); fmad2(u1[1], w1, sA.y);
    fmad2(u0[2], w0, sB.x); fmad2(u1[2], w1, sB.x);
    fmad2(u0[3], w0, sB.y); fmad2(u1[3], w1, sB.y);
    fmad2(u0[4], w0, sC.x); fmad2(u1[4], w1, sC.x);
    fmad2(u0[5], w0, sC.y); fmad2(u1[5], w1, sC.y);
    fmad2(u0[6], w0, sD.x); fmad2(u1[6], w1, sD.x);
    fmad2(u0[7], w0, sD.y); fmad2(u1[7], w1, sD.y);
}

// Fused 2-row GEMM over one K-chunk. Accumulators persist across chunks.
// SKIP: branch on quiet bytes (hidden layers, low spike density).
template <int K, bool SKIP>
__device__ __forceinline__ void gemm2(const ull* __restrict__ wbuf,
                                      const u16* __restrict__ sp,  // [K] pair bytes
                                      const ull* __restrict__ lut, int lane, ull* A0,
                                      ull* A1, ull* B0, ull* B1) {
    const ull* wk = wbuf + lane;
#pragma unroll 1
    for (int k4 = 0; k4 < K; k4 += 4) {
        ull b4 = *(const ull*)(sp + k4);  // 4 k's of row-pair bytes
        if (SKIP && b4 == 0ull) continue;
#pragma unroll
        for (int j = 0; j < 4; j++) {
            unsigned pr = (unsigned)(b4 >> (16 * j)) & 0xFFFFu;
            if (SKIP && pr == 0u) continue;
            ull w0 = wk[(k4 + j) * 64];
            ull w1 = wk[(k4 + j) * 64 + 32];
            if (!SKIP || (pr & 0xFFu))
                fma8(A0, A1, w0, w1, (const ulonglong2*)(lut + (pr & 0xFFu) * 8));
            if (!SKIP || (pr >> 8))
                fma8(B0, B1, w0, w1, (const ulonglong2*)(lut + (pr >> 8) * 8));
        }
    }
}

// Butterfly-reduce 8 floats across the warp.
__device__ __forceinline__ void wred8(float* p) {
#pragma unroll
    for (int off = 16; off > 0; off >>= 1) {
#pragma unroll
        for (int t = 0; t < Tn; t++)
            p[t] += __shfl_xor_sync(0xffffffffu, p[t], off);
    }
}

// LN + residual + LIF for one row given its accumulators; returns 4 spike bytes.
__device__ __forceinline__ void ln_lif_row(ull* u0, ull* u1, const float* cb,
                                           unsigned q0, unsigned q1, unsigned q2,
                                           unsigned q3, int lane, unsigned* nout) {
    float p[Tn];
#pragma unroll
    for (int t = 0; t < Tn; t++)
        p[t] = f2lo(u0[t]) + f2hi(u0[t]) + f2lo(u1[t]) + f2hi(u1[t]);
    wred8(p);
    float mu[Tn];
#pragma unroll
    for (int t = 0; t < Tn; t++) mu[t] = p[t] * (1.0f / 128.0f);
#pragma unroll
    for (int t = 0; t < Tn; t++) {
        float a = f2lo(u0[t]) - mu[t];
        float b = f2hi(u0[t]) - mu[t];
        float c = f2lo(u1[t]) - mu[t];
        float d = f2hi(u1[t]) - mu[t];
        p[t] = a * a + b * b + c * c + d * d;
    }
    wred8(p);
    const float g0 = cb[128 + lane],      g1 = cb[128 + lane + 64];
    const float g2 = cb[128 + lane + 32], g3 = cb[128 + lane + 96];
    const float e0 = cb[256 + lane],      e1 = cb[256 + lane + 64];
    const float e2 = cb[256 + lane + 32], e3 = cb[256 + lane + 96];
    float v0 = 0.f, v1 = 0.f, v2 = 0.f, v3 = 0.f;
    unsigned n0 = 0, n1 = 0, n2 = 0, n3 = 0;
#pragma unroll
    for (int t = 0; t < Tn; t++) {
        float rs = rsqrtf(p[t] * (1.0f / 128.0f) + 1e-5f);
        float y0 = (f2lo(u0[t]) - mu[t]) * rs * g0 + e0 + (float)((q0 >> t) & 1);
        float y1 = (f2hi(u0[t]) - mu[t]) * rs * g1 + e1 + (float)((q1 >> t) & 1);
        float y2 = (f2lo(u1[t]) - mu[t]) * rs * g2 + e2 + (float)((q2 >> t) & 1);
        float y3 = (f2hi(u1[t]) - mu[t]) * rs * g3 + e3 + (float)((q3 >> t) & 1);
        v0 += (y0 - v0) * 0.5f; if (v0 >= 1.f) { n0 |= 1u << t; v0 = 0.f; }
        v1 += (y1 - v1) * 0.5f; if (v1 >= 1.f) { n1 |= 1u << t; v1 = 0.f; }
        v2 += (y2 - v2) * 0.5f; if (v2 >= 1.f) { n2 |= 1u << t; v2 = 0.f; }
        v3 += (y3 - v3) * 0.5f; if (v3 >= 1.f) { n3 |= 1u << t; v3 = 0.f; }
    }
    nout[0] = n0; nout[1] = n1; nout[2] = n2; nout[3] = n3;
}

// Plain LIF (no LN/residual) for phase 1.
__device__ __forceinline__ void lif_row(ull* u0, ull* u1, unsigned* nout) {
    float v0 = 0.f, v1 = 0.f, v2 = 0.f, v3 = 0.f;
    unsigned n0 = 0, n1 = 0, n2 = 0, n3 = 0;
#pragma unroll
    for (int t = 0; t < Tn; t++) {
        float a = f2lo(u0[t]), b = f2hi(u0[t]);
        float c = f2lo(u1[t]), d = f2hi(u1[t]);
        v0 += (a - v0) * 0.5f; if (v0 >= 1.f) { n0 |= 1u << t; v0 = 0.f; }
        v1 += (b - v1) * 0.5f; if (v1 >= 1.f) { n1 |= 1u << t; v1 = 0.f; }
        v2 += (c - v2) * 0.5f; if (v2 >= 1.f) { n2 |= 1u << t; v2 = 0.f; }
        v3 += (d - v3) * 0.5f; if (v3 >= 1.f) { n3 |= 1u << t; v3 = 0.f; }
    }
    nout[0] = n0; nout[1] = n1; nout[2] = n2; nout[3] = n3;
}

// Write both rows' spike bytes as u16 pairs into [warp][128] layout.
__device__ __forceinline__ void store_pair(u16* hout, int warp, int lane,
                                           const unsigned* nA, const unsigned* nB) {
    u16* hp = hout + warp * Hn;
    hp[lane]      = (u16)(nA[0] | (nB[0] << 8));
    hp[lane + 64] = (u16)(nA[1] | (nB[1] << 8));
    hp[lane + 32] = (u16)(nA[2] | (nB[2] << 8));
    hp[lane + 96] = (u16)(nA[3] | (nB[3] << 8));
}

// Stage Kc rows of W (starting at global row k0) into the 64KB chunk buffer.
__device__ __forceinline__ void load_w_chunk(const float* __restrict__ W, int k0,
                                             int Kc, ull* wbuf) {
    float* wf = (float*)wbuf;
    for (int i = threadIdx.x; i < Kc * Hn; i += BLOCK) {
        int k = i >> 7;
        int h = i & 127;
        wf[(k * 64 + (h & 63)) * 2 + (h >> 6)] = W[(k0 + k) * Hn + h];
    }
}

__device__ __forceinline__ void load_cb3(const float* __restrict__ b,
                                         const float* __restrict__ g,
                                         const float* __restrict__ be, float* cb) {
    for (int i = threadIdx.x; i < Hn; i += BLOCK) {
        cb[i] = b[i];
        cb[128 + i] = g[i];
        cb[256 + i] = be[i];
    }
}

// One MS_ResBlock for the warp's row pair (SKIP on).
__device__ __forceinline__ void resblock2(const ull* __restrict__ wbuf,
                                          const float* __restrict__ cb,
                                          const ull* __restrict__ lut,
                                          const u16* __restrict__ hin,
                                          u16* __restrict__ hout, int warp, int lane) {
    const ull bi0 = pk(cb[lane], cb[lane + 64]);
    const ull bi1 = pk(cb[lane + 32], cb[lane + 96]);
    ull A0[Tn], A1[Tn], B0[Tn], B1[Tn];
#pragma unroll
    for (int t = 0; t < Tn; t++) { A0[t] = bi0; A1[t] = bi1; B0[t] = bi0; B1[t] = bi1; }
    gemm2<Hn, true>(wbuf, hin + warp * Hn, lut, lane, A0, A1, B0, B1);

    const u16* hp = hin + warp * Hn;
    unsigned p0 = hp[lane], p1 = hp[lane + 64], p2 = hp[lane + 32], p3 = hp[lane + 96];
    unsigned nA[4], nB[4];
    ln_lif_row(A0, A1, cb, p0 & 0xFFu, p1 & 0xFFu, p2 & 0xFFu, p3 & 0xFFu, lane, nA);
    ln_lif_row(B0, B1, cb, p0 >> 8, p1 >> 8, p2 >> 8, p3 >> 8, lane, nB);
    store_pair(hout, warp, lane, nA, nB);
}

__global__ __launch_bounds__(BLOCK, 2) void snn_kernel(
    const float* __restrict__ x, const float* __restrict__ enc,
    const float* __restrict__ W_in, const float* __restrict__ b_in,
    const float* __restrict__ W_r1, const float* __restrict__ b_r1,
    const float* __restrict__ g_r1, const float* __restrict__ be_r1,
    const float* __restrict__ W_r2, const float* __restrict__ b_r2,
    const float* __restrict__ g_r2, const float* __restrict__ be_r2,
    const float* __restrict__ W_out, const float* __restrict__ b_out,
    float* __restrict__ out) {
    extern __shared__ char smem[];
    ull* wbuf = (ull*)(smem + OFF_WBUF);
    u16* sIN = (u16*)(smem + OFF_SIN);
    u16* hA = (u16*)(smem + OFF_HA);
    u16* hB = (u16*)(smem + OFF_HB);
    float* wout = (float*)(smem + OFF_WOUT);
    float* bout = (float*)(smem + OFF_BOUT);
    float* cb = (float*)(smem + OFF_CB);
    ull* lut = (ull*)(smem + OFF_LUT);

    const int b0 = blockIdx.x * RPB;
    const int tid = threadIdx.x;
    const int warp = tid >> 5;
    const int lane = tid & 31;

    // Phase 0: spike LUT, vectorized Poisson encode (pair layout), stage constants
    for (int i = tid; i < 256 * 8; i += BLOCK) {
        int byte = i >> 3, t = i & 7;
        unsigned u = ((byte >> t) & 1) ? 0x3F800000u : 0u;
        lut[i] = ((ull)u << 32) | u;
    }
    for (int i = tid; i < 8 * 64; i += BLOCK) {
        int w = i >> 6;
        int s4 = (i & 63) * 4;
        int bA = b0 + 2 * w, bB = bA + 1;
        float4 xA = *(const float4*)(x + (size_t)bA * Sn + s4);
        float4 xB = *(const float4*)(x + (size_t)bB * Sn + s4);
        unsigned byA0 = 0, byA1 = 0, byA2 = 0, byA3 = 0;
        unsigned byB0 = 0, byB1 = 0, byB2 = 0, byB3 = 0;
#pragma unroll
        for (int t = 0; t < Tn; t++) {
            float4 eA = *(const float4*)(enc + ((size_t)t * Bn + bA) * Sn + s4);
            float4 eB = *(const float4*)(enc + ((size_t)t * Bn + bB) * Sn + s4);
            unsigned bit = 1u << t;
            if (eA.x <= xA.x) byA0 |= bit;
            if (eA.y <= xA.y) byA1 |= bit;
            if (eA.z <= xA.z) byA2 |= bit;
            if (eA.w <= xA.w) byA3 |= bit;
            if (eB.x <= xB.x) byB0 |= bit;
            if (eB.y <= xB.y) byB1 |= bit;
            if (eB.z <= xB.z) byB2 |= bit;
            if (eB.w <= xB.w) byB3 |= bit;
        }
        ull packed = (ull)(byA0 | (byB0 << 8)) | ((ull)(byA1 | (byB1 << 8)) << 16) |
                     ((ull)(byA2 | (byB2 << 8)) << 32) | ((ull)(byA3 | (byB3 << 8)) << 48);
        *(ull*)(sIN + w * Sn + s4) = packed;
    }
    for (int i = tid; i < Hn; i += BLOCK) cb[i] = b_in[i];
    for (int i = tid; i < Hn * An; i += BLOCK) wout[i] = W_out[i];
    if (tid < An) bout[tid] = b_out[tid];
    __syncthreads();

    // Phase 1: GEMM1 (S=256 -> H=128, two 128-k chunks) + LIF -> hA
    {
        const ull bi0 = pk(cb[lane], cb[lane + 64]);
        const ull bi1 = pk(cb[lane + 32], cb[lane + 96]);
        ull A0[Tn], A1[Tn], B0[Tn], B1[Tn];
#pragma unroll
        for (int t = 0; t < Tn; t++) { A0[t] = bi0; A1[t] = bi1; B0[t] = bi0; B1[t] = bi1; }
#pragma unroll 1
        for (int c = 0; c < 2; c++) {
            load_w_chunk(W_in, c * 128, 128, wbuf);
            __syncthreads();
            gemm2<128, false>(wbuf, sIN + warp * Sn + c * 128, lut, lane, A0, A1, B0, B1);
            __syncthreads();
        }
        unsigned nA[4], nB[4];
        lif_row(A0, A1, nA);
        lif_row(B0, B1, nB);
        store_pair(hA, warp, lane, nA, nB);
    }
    __syncthreads();

    // Phase 2: ResBlock 1
    load_w_chunk(W_r1, 0, Hn, wbuf);
    load_cb3(b_r1, g_r1, be_r1, cb);
    __syncthreads();
    resblock2(wbuf, cb, lut, hA, hB, warp, lane);
    __syncthreads();

    // Phase 3: ResBlock 2
    load_w_chunk(W_r2, 0, Hn, wbuf);
    load_cb3(b_r2, g_r2, be_r2, cb);
    __syncthreads();
    resblock2(wbuf, cb, lut, hB, hA, warp, lane);
    __syncthreads();

    // Phase 4: readout GEMM (H=128 -> A=18) + non-spiking LIF + time mean.
    const float WGT[Tn] = {255.f / 2048.f, 127.f / 1024.f, 63.f / 512.f, 31.f / 256.f,
                           15.f / 128.f,   7.f / 64.f,     3.f / 32.f,   1.f / 16.f};
    const unsigned char* hby = (const unsigned char*)hA;
    for (int task = tid; task < RPB * An; task += BLOCK) {
        int r = task / An;
        int a = task - r * An;
        float acc[Tn] = {0.f, 0.f, 0.f, 0.f, 0.f, 0.f, 0.f, 0.f};
        const unsigned char* hp = hby + (r >> 1) * 256 + (r & 1);
        for (int h = 0; h < Hn; h++) {
            unsigned byte = hp[h * 2];
            float w = wout[h * An + a];
#pragma unroll
            for (int t = 0; t < Tn; t++)
                if (byte & (1u << t)) acc[t] += w;
        }
        float bo = bout[a];
        float o = 0.f;
#pragma unroll
        for (int t = 0; t < Tn; t++) o += WGT[t] * (acc[t] + bo);
        out[(size_t)(b0 + r) * An + a] = o;
    }
}

extern "C" void kernel_launch(void* const* d_in, const int* in_sizes, int n_in,
                              void* d_out, int out_size) {
    const float* x     = (const float*)d_in[0];
    const float* enc   = (const float*)d_in[1];
    const float* W_in  = (const float*)d_in[2];
    const float* b_in  = (const float*)d_in[3];
    const float* W_r1  = (const float*)d_in[4];
    const float* b_r1  = (const float*)d_in[5];
    const float* g_r1  = (const float*)d_in[6];
    const float* be_r1 = (const float*)d_in[7];
    const float* W_r2  = (const float*)d_in[8];
    const float* g_r2p = (const float*)d_in[10];
    const float* b_r2  = (const float*)d_in[9];
    const float* be_r2 = (const float*)d_in[11];
    const float* W_out = (const float*)d_in[12];
    const float* b_out = (const float*)d_in[13];
    float* out = (float*)d_out;

    cudaFuncSetAttribute(snn_kernel, cudaFuncAttributeMaxDynamicSharedMemorySize,
                         SMEM_BYTES);
    // THE fix: force max L1/shared carveout so TWO 98.6KB CTAs co-reside per SM.
    cudaFuncSetAttribute(snn_kernel, cudaFuncAttributePreferredSharedMemoryCarveout,
                         100);
    snn_kernel<<<GRID, BLOCK, SMEM_BYTES>>>(x, enc, W_in, b_in, W_r1, b_r1, g_r1,
                                            be_r1, W_r2, b_r2, g_r2p, be_r2, W_out,
                                            b_out, out);
}

// round 15
// speedup vs baseline: 1.7048x; 1.0509x over previous
#include <cuda_runtime.h>
#include <cstdint>

// SNNQNet bit-exact scalar path, round 10: no weight staging, no block barriers
// in the compute phases. Weights pre-paired in GLOBAL memory (setup kernels),
// read via __ldg (L1-resident). Phases 1-3 are warp-independent (hA/hB are
// per-warp private) -> only __syncwarp between phases; fast warps run ahead.
// Same adds, same k-ascending order, same fma.rn.f32x2 => membranes
// bit-identical (rel_err 9.000283e-8).

constexpr int Bn = 16384;
constexpr int Sn = 256;
constexpr int Hn = 128;
constexpr int An = 18;
constexpr int Tn = 8;

constexpr int BLOCK = 256;       // 8 warps
constexpr int RPB   = 16;        // batch rows per block (2 per warp)
constexpr int GRID  = Bn / RPB;  // 1024

typedef unsigned long long ull;
typedef unsigned short u16;

// Pre-paired weights: dst[k*64+j] = { lo: W[k][j], hi: W[k][j+64] }
__device__ __align__(256) ull g_Wpk_in[Sn * 64];
__device__ __align__(256) ull g_Wpk_r1[Hn * 64];
__device__ __align__(256) ull g_Wpk_r2[Hn * 64];

__global__ void pack_kernel(const float* __restrict__ W, ull* __restrict__ dst,
                            int K) {
    int i = blockIdx.x * 256 + threadIdx.x;
    if (i >= K * 64) return;
    int k = i >> 6, j = i & 63;
    dst[i] = ((ull)__float_as_uint(W[k * Hn + j + 64]) << 32) |
             __float_as_uint(W[k * Hn + j]);
}

__device__ __forceinline__ float f2lo(ull v) { return __uint_as_float((unsigned)v); }
__device__ __forceinline__ float f2hi(ull v) { return __uint_as_float((unsigned)(v >> 32)); }
__device__ __forceinline__ ull pk(float a, float b) {
    return (ull)__float_as_uint(a) | ((ull)__float_as_uint(b) << 32);
}

__device__ __forceinline__ void fmad2(ull& u, ull w, ull s) {
    asm("fma.rn.f32x2 %0, %1, %2, %0;" : "+l"(u) : "l"(w), "l"(s));
}

// 16 fma2: 8 timesteps x 2 h-pairs, one k step, one row.
__device__ __forceinline__ void fma8(ull* u0, ull* u1, ull w0, ull w1,
                                     const ulonglong2* __restrict__ lp) {
    ulonglong2 sA = lp[0], sB = lp[1], sC = lp[2], sD = lp[3];
    fmad2(u0[0], w0, sA.x); fmad2(u1[0], w1, sA.x);
    fmad2(u0[1], w0, sA.y); fmad2(u1[1], w1, sA.y);
    fmad2(u0[2], w0, sB.x); fmad2(u1[2], w1, sB.x);
    fmad2(u0[3], w0, sB.y); fmad2(u1[3], w1, sB.y);
    fmad2(u0[4], w0, sC.x); fmad2(u1[4], w1, sC.x);
    fmad2(u0[5], w0, sC.y); fmad2(u1[5], w1, sC.y);
    fmad2(u0[6], w0, sD.x); fmad2(u1[6], w1, sD.x);
    fmad2(u0[7], w0, sD.y); fmad2(u1[7], w1, sD.y);
}

// Fused 2-row GEMM over K, weights from pre-paired GLOBAL memory via __ldg.
template <int K, bool SKIP>
__device__ __forceinline__ void gemm2g(const ull* __restrict__ wg,
                                       const u16* __restrict__ sp,  // [K] pair bytes
                                       const ull* __restrict__ lut, int lane, ull* A0,
                                       ull* A1, ull* B0, ull* B1) {
    const ull* wk = wg + lane;
#pragma unroll 1
    for (int k4 = 0; k4 < K; k4 += 4) {
        ull b4 = *(const ull*)(sp + k4);  // 4 k's of row-pair bytes
        if (SKIP && b4 == 0ull) continue;
#pragma unroll
        for (int j = 0; j < 4; j++) {
            unsigned pr = (unsigned)(b4 >> (16 * j)) & 0xFFFFu;
            if (SKIP && pr == 0u) continue;
            ull w0 = __ldg(wk + (k4 + j) * 64);
            ull w1 = __ldg(wk + (k4 + j) * 64 + 32);
            if (!SKIP || (pr & 0xFFu))
                fma8(A0, A1, w0, w1, (const ulonglong2*)(lut + (pr & 0xFFu) * 8));
            if (!SKIP || (pr >> 8))
                fma8(B0, B1, w0, w1, (const ulonglong2*)(lut + (pr >> 8) * 8));
        }
    }
}

// Butterfly-reduce 8 floats across the warp.
__device__ __forceinline__ void wred8(float* p) {
#pragma unroll
    for (int off = 16; off > 0; off >>= 1) {
#pragma unroll
        for (int t = 0; t < Tn; t++)
            p[t] += __shfl_xor_sync(0xffffffffu, p[t], off);
    }
}

// LN + residual + LIF for one row; returns 4 spike bytes.
__device__ __forceinline__ void ln_lif_row(ull* u0, ull* u1, const float* cb,
                                           unsigned q0, unsigned q1, unsigned q2,
                                           unsigned q3, int lane, unsigned* nout) {
    float p[Tn];
#pragma unroll
    for (int t = 0; t < Tn; t++)
        p[t] = f2lo(u0[t]) + f2hi(u0[t]) + f2lo(u1[t]) + f2hi(u1[t]);
    wred8(p);
    float mu[Tn];
#pragma unroll
    for (int t = 0; t < Tn; t++) mu[t] = p[t] * (1.0f / 128.0f);
#pragma unroll
    for (int t = 0; t < Tn; t++) {
        float a = f2lo(u0[t]) - mu[t];
        float b = f2hi(u0[t]) - mu[t];
        float c = f2lo(u1[t]) - mu[t];
        float d = f2hi(u1[t]) - mu[t];
        p[t] = a * a + b * b + c * c + d * d;
    }
    wred8(p);
    const float g0 = cb[128 + lane],      g1 = cb[128 + lane + 64];
    const float g2 = cb[128 + lane + 32], g3 = cb[128 + lane + 96];
    const float e0 = cb[256 + lane],      e1 = cb[256 + lane + 64];
    const float e2 = cb[256 + lane + 32], e3 = cb[256 + lane + 96];
    float v0 = 0.f, v1 = 0.f, v2 = 0.f, v3 = 0.f;
    unsigned n0 = 0, n1 = 0, n2 = 0, n3 = 0;
#pragma unroll
    for (int t = 0; t < Tn; t++) {
        float rs = rsqrtf(p[t] * (1.0f / 128.0f) + 1e-5f);
        float y0 = (f2lo(u0[t]) - mu[t]) * rs * g0 + e0 + (float)((q0 >> t) & 1);
        float y1 = (f2hi(u0[t]) - mu[t]) * rs * g1 + e1 + (float)((q1 >> t) & 1);
        float y2 = (f2lo(u1[t]) - mu[t]) * rs * g2 + e2 + (float)((q2 >> t) & 1);
        float y3 = (f2hi(u1[t]) - mu[t]) * rs * g3 + e3 + (float)((q3 >> t) & 1);
        v0 += (y0 - v0) * 0.5f; if (v0 >= 1.f) { n0 |= 1u << t; v0 = 0.f; }
        v1 += (y1 - v1) * 0.5f; if (v1 >= 1.f) { n1 |= 1u << t; v1 = 0.f; }
        v2 += (y2 - v2) * 0.5f; if (v2 >= 1.f) { n2 |= 1u << t; v2 = 0.f; }
        v3 += (y3 - v3) * 0.5f; if (v3 >= 1.f) { n3 |= 1u << t; v3 = 0.f; }
    }
    nout[0] = n0; nout[1] = n1; nout[2] = n2; nout[3] = n3;
}

// Plain LIF (no LN/residual) for phase 1.
__device__ __forceinline__ void lif_row(ull* u0, ull* u1, unsigned* nout) {
    float v0 = 0.f, v1 = 0.f, v2 = 0.f, v3 = 0.f;
    unsigned n0 = 0, n1 = 0, n2 = 0, n3 = 0;
#pragma unroll
    for (int t = 0; t < Tn; t++) {
        float a = f2lo(u0[t]), b = f2hi(u0[t]);
        float c = f2lo(u1[t]), d = f2hi(u1[t]);
        v0 += (a - v0) * 0.5f; if (v0 >= 1.f) { n0 |= 1u << t; v0 = 0.f; }
        v1 += (b - v1) * 0.5f; if (v1 >= 1.f) { n1 |= 1u << t; v1 = 0.f; }
        v2 += (c - v2) * 0.5f; if (v2 >= 1.f) { n2 |= 1u << t; v2 = 0.f; }
        v3 += (d - v3) * 0.5f; if (v3 >= 1.f) { n3 |= 1u << t; v3 = 0.f; }
    }
    nout[0] = n0; nout[1] = n1; nout[2] = n2; nout[3] = n3;
}

__device__ __forceinline__ void store_pair(u16* hout, int warp, int lane,
                                           const unsigned* nA, const unsigned* nB) {
    u16* hp = hout + warp * Hn;
    hp[lane]      = (u16)(nA[0] | (nB[0] << 8));
    hp[lane + 64] = (u16)(nA[1] | (nB[1] << 8));
    hp[lane + 32] = (u16)(nA[2] | (nB[2] << 8));
    hp[lane + 96] = (u16)(nA[3] | (nB[3] << 8));
}

// One MS_ResBlock for the warp's row pair (weights from global).
__device__ __forceinline__ void resblock2g(const ull* __restrict__ wg,
                                           const float* __restrict__ cb,
                                           const ull* __restrict__ lut,
                                           const u16* __restrict__ hin,
                                           u16* __restrict__ hout, int warp, int lane) {
    const ull bi0 = pk(cb[lane], cb[lane + 64]);
    const ull bi1 = pk(cb[lane + 32], cb[lane + 96]);
    ull A0[Tn], A1[Tn], B0[Tn], B1[Tn];
#pragma unroll
    for (int t = 0; t < Tn; t++) { A0[t] = bi0; A1[t] = bi1; B0[t] = bi0; B1[t] = bi1; }
    gemm2g<Hn, true>(wg, hin + warp * Hn, lut, lane, A0, A1, B0, B1);

    const u16* hp = hin + warp * Hn;
    unsigned p0 = hp[lane], p1 = hp[lane + 64], p2 = hp[lane + 32], p3 = hp[lane + 96];
    unsigned nA[4], nB[4];
    ln_lif_row(A0, A1, cb, p0 & 0xFFu, p1 & 0xFFu, p2 & 0xFFu, p3 & 0xFFu, lane, nA);
    ln_lif_row(B0, B1, cb, p0 >> 8, p1 >> 8, p2 >> 8, p3 >> 8, lane, nB);
    store_pair(hout, warp, lane, nA, nB);
    __syncwarp();
}

__global__ __launch_bounds__(BLOCK, 2) void snn_kernel(
    const float* __restrict__ x, const float* __restrict__ enc,
    const float* __restrict__ b_in, const float* __restrict__ b_r1,
    const float* __restrict__ g_r1, const float* __restrict__ be_r1,
    const float* __restrict__ b_r2, const float* __restrict__ g_r2,
    const float* __restrict__ be_r2, const float* __restrict__ W_out,
    const float* __restrict__ b_out, float* __restrict__ out) {
    __shared__ u16 sIN[8 * Sn];
    __shared__ u16 hA[8 * Hn];
    __shared__ u16 hB[8 * Hn];
    __shared__ float wout[Hn * An];
    __shared__ float bout[32];
    __shared__ float cb_in[128];
    __shared__ float cb_r1[384];
    __shared__ float cb_r2[384];
    __shared__ ull lut[256 * 8];

    const int b0 = blockIdx.x * RPB;
    const int tid = threadIdx.x;
    const int warp = tid >> 5;
    const int lane = tid & 31;

    // ---- Phase 0: LUT, encode, all constants. ONE block barrier total. ----
    for (int i = tid; i < 256 * 8; i += BLOCK) {
        int byte = i >> 3, t = i & 7;
        unsigned u = ((byte >> t) & 1) ? 0x3F800000u : 0u;
        lut[i] = ((ull)u << 32) | u;
    }
    for (int i = tid; i < 8 * 64; i += BLOCK) {
        int w = i >> 6;
        int s4 = (i & 63) * 4;
        int bA = b0 + 2 * w, bB = bA + 1;
        float4 xA = *(const float4*)(x + (size_t)bA * Sn + s4);
        float4 xB = *(const float4*)(x + (size_t)bB * Sn + s4);
        unsigned byA0 = 0, byA1 = 0, byA2 = 0, byA3 = 0;
        unsigned byB0 = 0, byB1 = 0, byB2 = 0, byB3 = 0;
#pragma unroll
        for (int t = 0; t < Tn; t++) {
            float4 eA = *(const float4*)(enc + ((size_t)t * Bn + bA) * Sn + s4);
            float4 eB = *(const float4*)(enc + ((size_t)t * Bn + bB) * Sn + s4);
            unsigned bit = 1u << t;
            if (eA.x <= xA.x) byA0 |= bit;
            if (eA.y <= xA.y) byA1 |= bit;
            if (eA.z <= xA.z) byA2 |= bit;
            if (eA.w <= xA.w) byA3 |= bit;
            if (eB.x <= xB.x) byB0 |= bit;
            if (eB.y <= xB.y) byB1 |= bit;
            if (eB.z <= xB.z) byB2 |= bit;
            if (eB.w <= xB.w) byB3 |= bit;
        }
        ull packed = (ull)(byA0 | (byB0 << 8)) | ((ull)(byA1 | (byB1 << 8)) << 16) |
                     ((ull)(byA2 | (byB2 << 8)) << 32) | ((ull)(byA3 | (byB3 << 8)) << 48);
        *(ull*)(sIN + w * Sn + s4) = packed;
    }
    for (int i = tid; i < Hn; i += BLOCK) {
        cb_in[i] = b_in[i];
        cb_r1[i] = b_r1[i]; cb_r1[128 + i] = g_r1[i]; cb_r1[256 + i] = be_r1[i];
        cb_r2[i] = b_r2[i]; cb_r2[128 + i] = g_r2[i]; cb_r2[256 + i] = be_r2[i];
    }
    for (int i = tid; i < Hn * An; i += BLOCK) wout[i] = W_out[i];
    if (tid < An) bout[tid] = b_out[tid];
    __syncthreads();

    // ---- Phases 1-3: fully warp-independent (hA/hB are per-warp private) ----
    {
        const ull bi0 = pk(cb_in[lane], cb_in[lane + 64]);
        const ull bi1 = pk(cb_in[lane + 32], cb_in[lane + 96]);
        ull A0[Tn], A1[Tn], B0[Tn], B1[Tn];
#pragma unroll
        for (int t = 0; t < Tn; t++) { A0[t] = bi0; A1[t] = bi1; B0[t] = bi0; B1[t] = bi1; }
        gemm2g<Sn, false>(g_Wpk_in, sIN + warp * Sn, lut, lane, A0, A1, B0, B1);
        unsigned nA[4], nB[4];
        lif_row(A0, A1, nA);
        lif_row(B0, B1, nB);
        store_pair(hA, warp, lane, nA, nB);
        __syncwarp();
    }
    resblock2g(g_Wpk_r1, cb_r1, lut, hA, hB, warp, lane);
    resblock2g(g_Wpk_r2, cb_r2, lut, hB, hA, warp, lane);
    __syncthreads();

    // ---- Phase 4: readout GEMM (H=128 -> A=18) + non-spiking LIF + time mean ----
    const float WGT[Tn] = {255.f / 2048.f, 127.f / 1024.f, 63.f / 512.f, 31.f / 256.f,
                           15.f / 128.f,   7.f / 64.f,     3.f / 32.f,   1.f / 16.f};
    const unsigned char* hby = (const unsigned char*)hA;
    for (int task = tid; task < RPB * An; task += BLOCK) {
        int r = task / An;
        int a = task - r * An;
        float acc[Tn] = {0.f, 0.f, 0.f, 0.f, 0.f, 0.f, 0.f, 0.f};
        const unsigned char* hp = hby + (r >> 1) * 256 + (r & 1);
        for (int h = 0; h < Hn; h++) {
            unsigned byte = hp[h * 2];
            float w = wout[h * An + a];
#pragma unroll
            for (int t = 0; t < Tn; t++)
                if (byte & (1u << t)) acc[t] += w;
        }
        float bo = bout[a];
        float o = 0.f;
#pragma unroll
        for (int t = 0; t < Tn; t++) o += WGT[t] * (acc[t] + bo);
        out[(size_t)(b0 + r) * An + a] = o;
    }
}

extern "C" void kernel_launch(void* const* d_in, const int* in_sizes, int n_in,
                              void* d_out, int out_size) {
    const float* x     = (const float*)d_in[0];
    const float* enc   = (const float*)d_in[1];
    const float* W_in  = (const float*)d_in[2];
    const float* b_in  = (const float*)d_in[3];
    const float* W_r1  = (const float*)d_in[4];
    const float* b_r1  = (const float*)d_in[5];
    const float* g_r1  = (const float*)d_in[6];
    const float* be_r1 = (const float*)d_in[7];
    const float* W_r2  = (const float*)d_in[8];
    const float* b_r2  = (const float*)d_in[9];
    const float* g_r2  = (const float*)d_in[10];
    const float* be_r2 = (const float*)d_in[11];
    const float* W_out = (const float*)d_in[12];
    const float* b_out = (const float*)d_in[13];
    float* out = (float*)d_out;

    ull *Wp_in, *Wp_r1, *Wp_r2;
    cudaGetSymbolAddress((void**)&Wp_in, g_Wpk_in);
    cudaGetSymbolAddress((void**)&Wp_r1, g_Wpk_r1);
    cudaGetSymbolAddress((void**)&Wp_r2, g_Wpk_r2);

    pack_kernel<<<(Sn * 64 + 255) / 256, 256>>>(W_in, Wp_in, Sn);
    pack_kernel<<<(Hn * 64 + 255) / 256, 256>>>(W_r1, Wp_r1, Hn);
    pack_kernel<<<(Hn * 64 + 255) / 256, 256>>>(W_r2, Wp_r2, Hn);
    snn_kernel<<<GRID, BLOCK>>>(x, enc, b_in, b_r1, g_r1, be_r1, b_r2, g_r2, be_r2,
                                W_out, b_out, out);
}